// round 15
// baseline (speedup 1.0000x reference)
#include <cuda_runtime.h>
#include <cuda_bf16.h>

#define B_  16
#define M_  512
#define S_  32
#define E_  128

// Scratch (allocation-free)
__device__ float g_memory[B_ * M_ * E_];
__device__ float g_output[B_ * M_ * E_];
__device__ float g_q0[B_ * E_];
__device__ float g_scores[B_ * M_];
__device__ float g_part[B_ * 8 * E_];
__device__ float g_x[B_ * E_];

// enc[s][e] = 1 + (e-63)*(s-15)/1024

// ---------------------------------------------------------------------------
// Kernel 1: query embedding -> g_q0. grid B, block 128.
// ---------------------------------------------------------------------------
__global__ void __launch_bounds__(128) query_kernel(
    const int* __restrict__ queries,
    const float* __restrict__ qtab,
    int Vm1)
{
    const int b = blockIdx.x;
    const int tid = threadIdx.x;

    __shared__ int qidx[S_];
    if (tid < S_) qidx[tid] = queries[b * S_ + tid];
    __syncthreads();

    float acc = 0.f;
    const float ef = (float)(tid - 63);
    #pragma unroll
    for (int s = 0; s < S_; ++s) {
        const int idx = qidx[s];
        const float v = (idx < Vm1) ? qtab[(size_t)idx * E_ + tid] : 0.f;
        const float enc = 1.f + ef * (float)(s - 15) * (1.0f / 1024.0f);
        acc += enc * v;
    }
    g_q0[b * E_ + tid] = acc;
}

// ---------------------------------------------------------------------------
// Kernel 2: story embeddings -> memory, output, fused hop-0 scores (vs g_q0).
// grid (M, B), block 128. At the LTS roofline — irreducible gather traffic.
// ---------------------------------------------------------------------------
__global__ void __launch_bounds__(128) embed_kernel(
    const int* __restrict__ stories,
    const float* __restrict__ stab,
    const float* __restrict__ otab,
    const float* __restrict__ mbias,
    int Vm1)
{
    const int m = blockIdx.x;
    const int b = blockIdx.y;
    const int tid = threadIdx.x;

    __shared__ int sidx[S_];
    __shared__ float red[2][4][E_];
    __shared__ float qsm[E_];
    __shared__ float wsum[4];

    if (tid < S_) sidx[tid] = stories[(b * M_ + m) * S_ + tid];
    qsm[tid] = g_q0[b * E_ + tid];
    __syncthreads();

    const int lane = tid & 31;
    const int grp  = tid >> 5;

    const float4* __restrict__ stab4 = reinterpret_cast<const float4*>(stab);
    const float4* __restrict__ otab4 = reinterpret_cast<const float4*>(otab);

    float am0 = 0.f, am1 = 0.f, am2 = 0.f, am3 = 0.f;
    float ao0 = 0.f, ao1 = 0.f, ao2 = 0.f, ao3 = 0.f;
    const float ef0 = (float)(lane * 4 - 63);

    #pragma unroll
    for (int it = 0; it < 8; ++it) {
        const int s = grp + it * 4;
        const int idx = sidx[s];
        float4 av = make_float4(0.f, 0.f, 0.f, 0.f);
        float4 ov = make_float4(0.f, 0.f, 0.f, 0.f);
        if (idx < Vm1) {
            const size_t ro = (size_t)idx * (E_ / 4) + lane;
            av = stab4[ro];
            ov = otab4[ro];
        }
        const float sf = (float)(s - 15) * (1.0f / 1024.0f);
        const float e0 = 1.f + ef0 * sf;
        const float e1 = 1.f + (ef0 + 1.f) * sf;
        const float e2 = 1.f + (ef0 + 2.f) * sf;
        const float e3 = 1.f + (ef0 + 3.f) * sf;
        am0 += e0 * av.x; am1 += e1 * av.y; am2 += e2 * av.z; am3 += e3 * av.w;
        ao0 += e0 * ov.x; ao1 += e1 * ov.y; ao2 += e2 * ov.z; ao3 += e3 * ov.w;
    }

    *reinterpret_cast<float4*>(&red[0][grp][lane * 4]) = make_float4(am0, am1, am2, am3);
    *reinterpret_cast<float4*>(&red[1][grp][lane * 4]) = make_float4(ao0, ao1, ao2, ao3);
    __syncthreads();

    const float mv = red[0][0][tid] + red[0][1][tid] + red[0][2][tid] + red[0][3][tid]
                   + mbias[m * E_ + tid];
    const float ov2 = red[1][0][tid] + red[1][1][tid] + red[1][2][tid] + red[1][3][tid];

    const size_t o = ((size_t)(b * M_ + m)) * E_ + tid;
    g_memory[o] = mv;
    g_output[o] = ov2;

    float sv = mv * qsm[tid];
    #pragma unroll
    for (int off = 16; off; off >>= 1)
        sv += __shfl_xor_sync(0xffffffffu, sv, off);
    if (lane == 0) wsum[grp] = sv;
    __syncthreads();
    if (tid == 0)
        g_scores[b * M_ + m] = wsum[0] + wsum[1] + wsum[2] + wsum[3];
}

// ---------------------------------------------------------------------------
// Kernel 3: ALL 3 hops in one launch. grid (8, B), cluster (8,1,1) = one
// cluster per batch. block 512. Cross-seg data via global + cluster.sync.
// ---------------------------------------------------------------------------
__global__ void __launch_bounds__(512) __cluster_dims__(8, 1, 1)
hops_cluster(const float* __restrict__ wi,
             const float* __restrict__ wo)
{
    const int b   = blockIdx.y;
    const int seg = blockIdx.x;
    const int tid = threadIdx.x;
    const int lane = tid & 31;
    const int wid  = tid >> 5;
    const int e    = tid & 127;
    const int qt   = tid >> 7;

    __shared__ float q[E_];
    __shared__ float sp[M_];
    __shared__ float xs[E_];
    __shared__ float red[512];
    __shared__ float wred[16];
    __shared__ float bc;
    __shared__ float spart[4][16][33];

    if (tid < E_) q[tid] = g_q0[b * E_ + tid];
    __syncthreads();

    for (int hop = 0; hop < 3; ++hop) {
        const float* __restrict__ W = (hop == 2) ? wo : wi;

        // --- softmax over 512 scores (1 per thread, redundant per CTA) ---
        const float v = g_scores[b * M_ + tid];
        float lm = v;
        #pragma unroll
        for (int off = 16; off; off >>= 1)
            lm = fmaxf(lm, __shfl_xor_sync(0xffffffffu, lm, off));
        if (lane == 0) wred[wid] = lm;
        __syncthreads();
        if (tid == 0) {
            float mx = wred[0];
            #pragma unroll
            for (int i = 1; i < 16; ++i) mx = fmaxf(mx, wred[i]);
            bc = mx;
        }
        __syncthreads();
        const float p = __expf(v - bc);
        sp[tid] = p;
        float ls = p;
        #pragma unroll
        for (int off = 16; off; off >>= 1)
            ls += __shfl_xor_sync(0xffffffffu, ls, off);
        if (lane == 0) wred[wid] = ls;
        __syncthreads();
        if (tid == 0) {
            float sm = 0.f;
            #pragma unroll
            for (int i = 0; i < 16; ++i) sm += wred[i];
            bc = 1.0f / sm;
        }
        __syncthreads();
        const float inv = bc;

        // --- layerout partial: seg's 64 m rows, m split across 4 quarters ---
        {
            const float* __restrict__ op =
                g_output + ((size_t)b * M_ + seg * 64 + qt * 16) * E_ + e;
            const float* __restrict__ pp = &sp[seg * 64 + qt * 16];
            float acc = 0.f;
            #pragma unroll
            for (int m = 0; m < 16; ++m)
                acc += pp[m] * op[(size_t)m * E_];
            red[tid] = acc;
        }
        __syncthreads();
        if (tid < E_)
            g_part[((size_t)b * 8 + seg) * E_ + tid] =
                (red[tid] + red[tid + 128] + red[tid + 256] + red[tid + 384]) * inv;

        __threadfence();
        asm volatile("barrier.cluster.arrive.aligned;" ::: "memory");
        asm volatile("barrier.cluster.wait.aligned;" ::: "memory");

        // --- xs = q + sum of 8 partials (redundant per CTA) ---
        if (tid < E_) {
            float xv = q[tid];
            const float* __restrict__ pp = g_part + (size_t)b * 8 * E_ + tid;
            #pragma unroll
            for (int s = 0; s < 8; ++s) xv += pp[s * E_];
            xs[tid] = xv;
        }
        __syncthreads();

        // --- newq = xs @ W (k split 4 ways, fully unrolled 32-load slices) ---
        {
            const float* __restrict__ Wc = W + (size_t)(qt * 32) * E_ + e;
            const float* __restrict__ xp = &xs[qt * 32];
            float a = 0.f;
            #pragma unroll
            for (int k = 0; k < 32; ++k)
                a += xp[k] * Wc[(size_t)k * E_];
            red[tid] = a;
        }
        __syncthreads();
        if (tid < E_) {
            const float nq = red[tid] + red[tid + 128] + red[tid + 256] + red[tid + 384];
            q[tid] = (hop == 2) ? fmaxf(nq, 0.f) : nq;
        }
        __syncthreads();

        if (hop < 2) {
            // --- next-hop score slice for seg's 64 m rows (warps 0-3) ---
            if (wid < 4) {
                const float q0 = q[lane];
                const float q1 = q[lane + 32];
                const float q2 = q[lane + 64];
                const float q3 = q[lane + 96];
                const float* __restrict__ mem =
                    g_memory + ((size_t)b * M_ + seg * 64 + wid * 16) * E_;
                #pragma unroll
                for (int i = 0; i < 16; ++i) {
                    const float* __restrict__ r = mem + i * E_;
                    spart[wid][i][lane] = r[lane] * q0 + r[lane + 32] * q1
                                        + r[lane + 64] * q2 + r[lane + 96] * q3;
                }
                __syncwarp();
                if (lane < 16) {
                    float s = 0.f;
                    #pragma unroll
                    for (int l = 0; l < 32; ++l) s += spart[wid][lane][l];
                    g_scores[b * M_ + seg * 64 + wid * 16 + lane] = s;
                }
            }
            __threadfence();
            asm volatile("barrier.cluster.arrive.aligned;" ::: "memory");
            asm volatile("barrier.cluster.wait.aligned;" ::: "memory");
        }
    }

    if (seg == 0 && tid < E_)
        g_x[b * E_ + tid] = q[tid];   // already relu'd at hop 2
}

// ---------------------------------------------------------------------------
// Kernel 4: out[b,v] = relu_x[b,:] @ w_final[:,v].
// grid 250, block 512. e split 4 ways x 32 fully-unrolled loads (MLP=32).
// ---------------------------------------------------------------------------
__global__ void __launch_bounds__(512) final_kernel(
    const float* __restrict__ wf,
    float* __restrict__ out,
    int V)
{
    __shared__ float xsm[E_][B_];            // xsm[e][b]
    __shared__ float partial[4][128][B_];    // [qt][v_local][b]

    const int tid = threadIdx.x;
    const int vl  = tid & 127;
    const int qt  = tid >> 7;

    for (int i = tid; i < B_ * E_; i += 512) {
        const int b = i >> 7;
        const int e = i & 127;
        xsm[e][b] = g_x[i];
    }
    __syncthreads();

    const int v = blockIdx.x * 128 + vl;
    if (v < V) {
        float acc[B_];
        #pragma unroll
        for (int b = 0; b < B_; ++b) acc[b] = 0.f;

        const float* __restrict__ wp = wf + (size_t)(qt * 32) * V + v;
        #pragma unroll
        for (int k = 0; k < 32; ++k) {
            const float w = wp[(size_t)k * V];
            const int e = qt * 32 + k;
            #pragma unroll
            for (int b = 0; b < B_; ++b)
                acc[b] += xsm[e][b] * w;
        }

        #pragma unroll
        for (int b4 = 0; b4 < 4; ++b4)
            *reinterpret_cast<float4*>(&partial[qt][vl][b4 * 4]) =
                make_float4(acc[b4 * 4], acc[b4 * 4 + 1],
                            acc[b4 * 4 + 2], acc[b4 * 4 + 3]);
    }
    __syncthreads();

    if (qt == 0 && v < V) {
        #pragma unroll
        for (int b = 0; b < B_; ++b) {
            const float r = partial[0][vl][b] + partial[1][vl][b]
                          + partial[2][vl][b] + partial[3][vl][b];
            out[(size_t)b * V + v] = r;
        }
    }
}

// ---------------------------------------------------------------------------
extern "C" void kernel_launch(void* const* d_in, const int* in_sizes, int n_in,
                              void* d_out, int out_size)
{
    const int*   queries = (const int*)d_in[0];
    const int*   stories = (const int*)d_in[1];
    const float* qb      = (const float*)d_in[2];
    const float* sb      = (const float*)d_in[3];
    const float* mb      = (const float*)d_in[4];
    const float* ob      = (const float*)d_in[5];
    const float* wi      = (const float*)d_in[6];
    const float* wo      = (const float*)d_in[7];
    const float* wf      = (const float*)d_in[8];

    const int Vm1 = in_sizes[2] / E_;
    const int V   = out_size / B_;

    query_kernel<<<B_, 128>>>(queries, qb, Vm1);
    embed_kernel<<<dim3(M_, B_), 128>>>(stories, sb, ob, mb, Vm1);
    hops_cluster<<<dim3(8, B_), 512>>>(wi, wo);
    final_kernel<<<(V + 127) / 128, 512>>>(wf, (float*)d_out, V);
}